// round 14
// baseline (speedup 1.0000x reference)
#include <cuda_runtime.h>
#include <cuda_bf16.h>

// Integrate-and-fire spiking neuron, 3 phases, per-pixel independent.
// T1 = T2 = 8, L = 8, EPS = -8e-5, thre = thresh[0]/8.
//
// x layout:   x[t*S + p]  for t in [0,8), p in [0,S), S = B*C*H*W
// out layout: out[t*S + p]
//
// R13: 256-bit loads. sm_103a accepts ld.global.nc.v8.b32 (LDG.256 — the
// R9 ptxas diagnostic confirmed the form). Each thread now owns 8
// contiguous pixels: one v8 load per frame (8 LDGs/thread total, halved),
// each warp load = 1024 contiguous bytes = 8 full 128B lines. MLP=1/thread
// suffices: 64 warps/SM x 256B = 16KB outstanding >> ~8KB needed to cover
// DRAM latency, so registers stay ~32 and occupancy ~80%.
// Stores remain paired __stcs float4 (STG.256 unconfirmed on sm_103a).

#define IF_T1 8
#define IF_T2 8
#define IF_RELAX 7            // T3 - 1 = max(T1,T2) - 1
#define IF_EPS (-8e-05f)

// 256-bit global load (LDG.256), non-coherent path.
__device__ __forceinline__ void ldg256(const float* p, float v[8]) {
    unsigned int r0, r1, r2, r3, r4, r5, r6, r7;
    asm volatile("ld.global.nc.v8.b32 {%0,%1,%2,%3,%4,%5,%6,%7}, [%8];"
                 : "=r"(r0), "=r"(r1), "=r"(r2), "=r"(r3),
                   "=r"(r4), "=r"(r5), "=r"(r6), "=r"(r7)
                 : "l"(p));
    v[0] = __uint_as_float(r0); v[1] = __uint_as_float(r1);
    v[2] = __uint_as_float(r2); v[3] = __uint_as_float(r3);
    v[4] = __uint_as_float(r4); v[5] = __uint_as_float(r5);
    v[6] = __uint_as_float(r6); v[7] = __uint_as_float(r7);
}

__global__ __launch_bounds__(128)
void IF_88957362634870_kernel(const float* __restrict__ x,
                              const float* __restrict__ thresh,
                              float* __restrict__ out,
                              int S) {
    int base = (blockIdx.x * 128 + threadIdx.x) * 8;   // 8 pixels per thread
    if (base >= S) return;

    // thresh/L with L=8: *0.125f is exact (power of two), matches JAX fp32.
    const float thre = __ldg(thresh) * 0.125f;

    float mem[8], sc[8];
#pragma unroll
    for (int c = 0; c < 8; c++) {
        mem[c] = 0.5f * thre;
        sc[c]  = 0.0f;
    }

    // ---- Phase 1: integrate-and-fire over T1 frames ----
    // One LDG.256 per frame; consume immediately (MLP=1/thread is enough
    // at 64 warps/SM; keeps regs ~32 and occupancy high).
#pragma unroll
    for (int t = 0; t < IF_T1; t++) {
        float xv[8];
        ldg256(x + t * S + base, xv);
#pragma unroll
        for (int c = 0; c < 8; c++) {
            mem[c] = mem[c] + xv[c];
            float spike = ((mem[c] - thre) >= IF_EPS) ? thre : 0.0f;
            mem[c] = mem[c] - spike;
            sc[c]  = sc[c] + spike;
        }
    }

    // ---- Phase 2: T3-1 relaxation steps with reverse spikes ----
#pragma unroll
    for (int s = 0; s < IF_RELAX; s++) {
#pragma unroll
        for (int c = 0; c < 8; c++) {
            float spike = ((mem[c] - thre) >= IF_EPS) ? thre : 0.0f;
            float rev   = ((-mem[c]) > 0.0f) ? thre : 0.0f;
            mem[c] = (mem[c] - spike) + rev;   // same assoc order as JAX
            sc[c]  = (sc[c] + spike) - rev;
        }
    }

    // ---- Phase 3: re-emit spike count as T2 output spikes ----
    // Output is write-once, never re-read: evict-first streaming stores.
#pragma unroll
    for (int c = 0; c < 8; c++) mem[c] = sc[c];

#pragma unroll
    for (int t = 0; t < IF_T2; t++) {
        float sp[8];
#pragma unroll
        for (int c = 0; c < 8; c++) {
            sp[c]  = ((mem[c] - thre) >= IF_EPS) ? thre : 0.0f;
            mem[c] = mem[c] - sp[c];
        }
        float4 a, b;
        a.x = sp[0]; a.y = sp[1]; a.z = sp[2]; a.w = sp[3];
        b.x = sp[4]; b.y = sp[5]; b.z = sp[6]; b.w = sp[7];
        __stcs((float4*)(out + t * S + base),     a);
        __stcs((float4*)(out + t * S + base + 4), b);
    }
}

extern "C" void kernel_launch(void* const* d_in, const int* in_sizes, int n_in,
                              void* d_out, int out_size) {
    const float* x      = (const float*)d_in[0];
    const float* thresh = (const float*)d_in[1];
    float*       out    = (float*)d_out;

    int S  = in_sizes[0] / IF_T1;        // elements per frame
    int S8 = S / 8;                      // 8 pixels per thread

    int threads = 128;
    int blocks  = (S8 + threads - 1) / threads;
    IF_88957362634870_kernel<<<blocks, threads>>>(x, thresh, out, S);
}

// round 15
// speedup vs baseline: 1.0512x; 1.0512x over previous
#include <cuda_runtime.h>
#include <cuda_bf16.h>

// Integrate-and-fire spiking neuron, 3 phases, per-pixel independent.
// T1 = T2 = 8, L = 8, EPS = -8e-5, thre = thresh[0]/8.
//
// x layout:   x[t*S + p]   for t in [0,8), p in [0, S) with S = B*C*H*W
// out layout: out[t*S + p]
//
// R14: revert R13's LDG.256 (regs 54 / occ 46% — per-thread state blowup;
// warp count is this kernel's latency-hiding mechanism). Back to the best
// shape (4 px/thread, 128-thr blocks, __ldcs/__stcs, 32 regs), now as a
// PERSISTENT GRID-STRIDE kernel: exactly one resident wave
// (152 SMs x 16 blocks = 2432 CTAs), each thread walks ~3-4 tiles.
// Removes (n_waves-1)*T_wave_trans wave-transition overhead and CTA
// launch/drain churn of the 8192-CTA / 7-wave launch.

#define IF_T1 8
#define IF_T2 8
#define IF_RELAX 7            // T3 - 1 = max(T1,T2) - 1
#define IF_EPS (-8e-05f)

#define IF_BLOCKS 2432        // 152 SMs * 16 resident blocks (128 thr, 32 reg)
#define IF_THREADS 128

__global__ __launch_bounds__(IF_THREADS)
void IF_88957362634870_kernel(const float4* __restrict__ x,
                              const float* __restrict__ thresh,
                              float4* __restrict__ out,
                              int S4) {
    // thresh/L with L=8: *0.125f is exact (power of two), matches JAX fp32.
    const float thre = __ldg(thresh) * 0.125f;

    const int stride = IF_BLOCKS * IF_THREADS;

    for (int i = blockIdx.x * IF_THREADS + threadIdx.x; i < S4; i += stride) {
        float mem[4], sc[4];
#pragma unroll
        for (int c = 0; c < 4; c++) {
            mem[c] = 0.5f * thre;
            sc[c]  = 0.0f;
        }

        // ---- Phase 1: integrate-and-fire over T1 frames ----
        // Two batches of 4 front-batched LDG.128s (MLP=4) fit 32 regs.
#pragma unroll
        for (int half = 0; half < 2; half++) {
            float4 xs[4];
#pragma unroll
            for (int t = 0; t < 4; t++) {
                xs[t] = __ldcs(&x[i + (half * 4 + t) * S4]);
            }
#pragma unroll
            for (int t = 0; t < 4; t++) {
                float xv[4] = {xs[t].x, xs[t].y, xs[t].z, xs[t].w};
#pragma unroll
                for (int c = 0; c < 4; c++) {
                    mem[c] = mem[c] + xv[c];
                    float spike = ((mem[c] - thre) >= IF_EPS) ? thre : 0.0f;
                    mem[c] = mem[c] - spike;
                    sc[c]  = sc[c] + spike;
                }
            }
        }

        // ---- Phase 2: T3-1 relaxation steps with reverse spikes ----
#pragma unroll
        for (int s = 0; s < IF_RELAX; s++) {
#pragma unroll
            for (int c = 0; c < 4; c++) {
                float spike = ((mem[c] - thre) >= IF_EPS) ? thre : 0.0f;
                float rev   = ((-mem[c]) > 0.0f) ? thre : 0.0f;
                mem[c] = (mem[c] - spike) + rev;   // same assoc order as JAX
                sc[c]  = (sc[c] + spike) - rev;
            }
        }

        // ---- Phase 3: re-emit spike count as T2 output spikes ----
        // Output is write-once, never re-read: evict-first streaming stores.
#pragma unroll
        for (int c = 0; c < 4; c++) mem[c] = sc[c];

#pragma unroll
        for (int t = 0; t < IF_T2; t++) {
            float sp[4];
#pragma unroll
            for (int c = 0; c < 4; c++) {
                sp[c]  = ((mem[c] - thre) >= IF_EPS) ? thre : 0.0f;
                mem[c] = mem[c] - sp[c];
            }
            float4 o;
            o.x = sp[0]; o.y = sp[1]; o.z = sp[2]; o.w = sp[3];
            __stcs(&out[i + t * S4], o);
        }
    }
}

extern "C" void kernel_launch(void* const* d_in, const int* in_sizes, int n_in,
                              void* d_out, int out_size) {
    const float4* x      = (const float4*)d_in[0];
    const float*  thresh = (const float*)d_in[1];
    float4*       out    = (float4*)d_out;

    // Elements per frame: total / T1; float4s per frame: /4.
    int S  = in_sizes[0] / IF_T1;
    int S4 = S / 4;

    IF_88957362634870_kernel<<<IF_BLOCKS, IF_THREADS>>>(x, thresh, out, S4);
}